// round 4
// baseline (speedup 1.0000x reference)
#include <cuda_runtime.h>
#include <math.h>

#define NF     33
#define NPIX   16384
#define NCOEF  672
#define PITCH  129           // float2 pitch for row tiles
#define NCH    64            // split-K chunks in gemm (256 px each)

__device__ __align__(256) float2 XfTmp_g[2 * NPIX];
__device__ __align__(256) float2 Xf_g[2 * NPIX];       // fft2(x), digit-reversed
__device__ __align__(256) float  Fperm_g[NF * NPIX];   // filters, digit-reversed
__device__ __align__(256) float2 T_g[2 * NF * NPIX];   // phase temp (in-place for B)
__device__ __align__(256) float  G_g[2 * NF * NPIX];   // Re(conj(Xf) * XAf)
__device__ __align__(256) float  partial_g[2 * NF * NF * NCH];

__device__ __forceinline__ float2 cmulf(float2 a, float2 b) {
    return make_float2(fmaf(a.x, b.x, -a.y * b.y), fmaf(a.x, b.y, a.y * b.x));
}

// inverse of the DIF(4,4,4,2) digit-reversal: storage pos -> natural freq
__device__ __forceinline__ int invp(int s) {
    return (s >> 5) + (((s >> 3) & 3) << 2) + (((s >> 1) & 3) << 4) + ((s & 1) << 6);
}

__device__ __forceinline__ void init_W(float2* W, int tid) {
    if (tid < 128) {
        float s, c;
        sincosf(-2.0f * 3.14159265358979323846f * (float)tid / 128.0f, &s, &c);
        W[tid] = make_float2(c, s);
    }
}

// Radix-4 sweep over nlines lines of a 128-point axis.
// addr(line, pos) = line*sl + pos*sp. DIF: twiddle after DFT; DIT: before.
template<bool INV, bool DIT>
__device__ __forceinline__ void sweep_r4(float2* t, const float2* W,
                                         int log2nl, int sl, int sp,
                                         int log2L, int tid, int nthr)
{
    int nlines = 1 << log2nl;
    int total  = nlines << 5;
    int lQ = log2L - 2;
    int Qs = (1 << lQ) * sp;
    __syncthreads();
    for (int q = tid; q < total; q += nthr) {
        int line = q & (nlines - 1);
        int bf   = q >> log2nl;
        int p = bf & ((1 << lQ) - 1);
        int g = bf >> lQ;
        int a = line * sl + ((g << log2L) + p) * sp;
        float2 x0 = t[a], x1 = t[a + Qs], x2 = t[a + 2 * Qs], x3 = t[a + 3 * Qs];
        int e = p << (7 - log2L);
        float2 w1 = W[e], w2 = W[2 * e], w3 = W[3 * e];
        if (INV) { w1.y = -w1.y; w2.y = -w2.y; w3.y = -w3.y; }
        if (DIT) { x1 = cmulf(x1, w1); x2 = cmulf(x2, w2); x3 = cmulf(x3, w3); }
        float2 t0 = make_float2(x0.x + x2.x, x0.y + x2.y);
        float2 t1 = make_float2(x0.x - x2.x, x0.y - x2.y);
        float2 t2 = make_float2(x1.x + x3.x, x1.y + x3.y);
        float2 t3 = make_float2(x1.x - x3.x, x1.y - x3.y);
        float2 y0 = make_float2(t0.x + t2.x, t0.y + t2.y);
        float2 y2 = make_float2(t0.x - t2.x, t0.y - t2.y);
        float2 y1, y3;
        if (!INV) { y1 = make_float2(t1.x + t3.y, t1.y - t3.x);
                    y3 = make_float2(t1.x - t3.y, t1.y + t3.x); }
        else      { y1 = make_float2(t1.x - t3.y, t1.y + t3.x);
                    y3 = make_float2(t1.x + t3.y, t1.y - t3.x); }
        if (!DIT) { y1 = cmulf(y1, w1); y2 = cmulf(y2, w2); y3 = cmulf(y3, w3); }
        t[a] = y0; t[a + Qs] = y1; t[a + 2 * Qs] = y2; t[a + 3 * Qs] = y3;
    }
}

// Radix-2 sweep (L=2): no twiddle, identical for DIF/DIT, fwd/inv.
__device__ __forceinline__ void sweep_r2(float2* t, int log2nl, int sl, int sp,
                                         int tid, int nthr)
{
    int nlines = 1 << log2nl;
    int total  = nlines << 6;
    __syncthreads();
    for (int q = tid; q < total; q += nthr) {
        int line = q & (nlines - 1);
        int bf   = q >> log2nl;
        int a = line * sl + (2 * bf) * sp;
        float2 x0 = t[a], x1 = t[a + sp];
        t[a]      = make_float2(x0.x + x1.x, x0.y + x1.y);
        t[a + sp] = make_float2(x0.x - x1.x, x0.y - x1.y);
    }
}

// ---------- kernel: blocks 0..65: filter permute; 66..81: fft rows of x ----------
__global__ void __launch_bounds__(256) combo_kernel(const float* __restrict__ x,
                                                    const float* __restrict__ filters)
{
    __shared__ float2 W[128];
    __shared__ float2 tile[16 * PITCH];
    int tid = threadIdx.x;
    int blk = blockIdx.x;
    if (blk < 2 * NF) {
        int i  = blk >> 1;
        int s0 = (blk & 1) * 8192;
        for (int q = tid; q < 8192; q += 256) {
            int s = s0 + q;
            int kr = invp(s >> 7), kc = invp(s & 127);
            Fperm_g[i * NPIX + s] = __ldg(&filters[i * NPIX + kr * 128 + kc]);
        }
        return;
    }
    int idx = blk - 2 * NF;           // 0..15
    init_W(W, tid);
    int b = idx >> 3, r0 = (idx & 7) * 16;
    for (int q = tid; q < 16 * 128; q += 256) {
        int r = q >> 7, c = q & 127;
        tile[r * PITCH + c] = make_float2(x[b * NPIX + (r0 + r) * 128 + c], 0.0f);
    }
    sweep_r4<false,false>(tile, W, 4, PITCH, 1, 7, tid, 256);
    sweep_r4<false,false>(tile, W, 4, PITCH, 1, 5, tid, 256);
    sweep_r4<false,false>(tile, W, 4, PITCH, 1, 3, tid, 256);
    sweep_r2(tile, 4, PITCH, 1, tid, 256);
    __syncthreads();
    for (int q = tid; q < 16 * 128; q += 256) {
        int r = q >> 7, c = q & 127;
        XfTmp_g[b * NPIX + (r0 + r) * 128 + c] = tile[r * PITCH + c];
    }
}

// ---------- kernel: forward DIF along columns of x ----------
__global__ void __launch_bounds__(256) fft_cols_kernel()
{
    __shared__ float2 W[128];
    __shared__ float2 tile[128 * 17];
    int tid = threadIdx.x;
    init_W(W, tid);
    int b = blockIdx.x >> 3, c0 = (blockIdx.x & 7) * 16;
    for (int q = tid; q < 128 * 16; q += 256) {
        int pos = q >> 4, col = q & 15;
        tile[pos * 17 + col] = XfTmp_g[b * NPIX + pos * 128 + c0 + col];
    }
    sweep_r4<false,false>(tile, W, 4, 1, 17, 7, tid, 256);
    sweep_r4<false,false>(tile, W, 4, 1, 17, 5, tid, 256);
    sweep_r4<false,false>(tile, W, 4, 1, 17, 3, tid, 256);
    sweep_r2(tile, 4, 1, 17, tid, 256);
    __syncthreads();
    for (int q = tid; q < 128 * 16; q += 256) {
        int pos = q >> 4, col = q & 15;
        Xf_g[b * NPIX + pos * 128 + c0 + col] = tile[pos * 17 + col];
    }
}

// ---------- phase A: load F*Xf row-slab, inverse row FFT (DIT), write T ----------
__global__ void __launch_bounds__(256) scatA_kernel()
{
    __shared__ float2 W[128];
    __shared__ float2 tile[32 * PITCH];
    int tid = threadIdx.x;
    init_W(W, tid);
    int bi = blockIdx.x >> 2, slab = blockIdx.x & 3;
    int b = (bi >= NF) ? 1 : 0;
    int i = bi - b * NF;
    int r0 = slab * 32;
    const float2* Xf = Xf_g + b * NPIX;
    const float*  Fp = Fperm_g + i * NPIX;

    // fused load + filter mult + first DIT stage (r2 along row)
    __syncthreads();
    for (int q = tid; q < 2048; q += 256) {
        int line = q >> 6, bf = q & 63;
        int c0 = 2 * bf;
        int q0 = (r0 + line) * 128 + c0;
        float4 Xp = *(const float4*)&Xf[q0];
        float2 fp = *(const float2*)&Fp[q0];
        float2 a0 = make_float2(fp.x * Xp.x, fp.x * Xp.y);
        float2 a1 = make_float2(fp.y * Xp.z, fp.y * Xp.w);
        tile[line * PITCH + c0]     = make_float2(a0.x + a1.x, a0.y + a1.y);
        tile[line * PITCH + c0 + 1] = make_float2(a0.x - a1.x, a0.y - a1.y);
    }
    sweep_r4<true,true>(tile, W, 5, PITCH, 1, 3, tid, 256);
    sweep_r4<true,true>(tile, W, 5, PITCH, 1, 5, tid, 256);
    sweep_r4<true,true>(tile, W, 5, PITCH, 1, 7, tid, 256);
    __syncthreads();
    for (int q = tid; q < 4096; q += 256) {
        int line = q >> 7, c = q & 127;
        T_g[bi * NPIX + (r0 + line) * 128 + c] = tile[line * PITCH + c];
    }
}

// ---------- phase B: per col-slab: inv col FFT (DIT) + abs_eps + fwd col FFT (DIF), in place ----------
__global__ void __launch_bounds__(256) scatB_kernel()
{
    __shared__ float2 W[128];
    __shared__ float2 tile[128 * 33];   // addr = col + pos*33
    int tid = threadIdx.x;
    init_W(W, tid);
    int bi = blockIdx.x >> 2, slab = blockIdx.x & 3;
    int c0 = slab * 32;

    __syncthreads();
    for (int q = tid; q < 4096; q += 256) {
        int col = q & 31, pos = q >> 5;
        tile[col + pos * 33] = T_g[bi * NPIX + pos * 128 + c0 + col];
    }
    // inverse DIT along pos
    sweep_r2(tile, 5, 1, 33, tid, 256);
    sweep_r4<true,true>(tile, W, 5, 1, 33, 3, tid, 256);
    sweep_r4<true,true>(tile, W, 5, 1, 33, 5, tid, 256);
    // last DIT stage (L=128) fused with abs_eps (+ 1/16384 ifft normalization)
    {
        const float s = 1.0f / 16384.0f;
        __syncthreads();
        for (int q = tid; q < 1024; q += 256) {
            int col = q & 31;
            int p   = q >> 5;              // 0..31
            int a = col + p * 33;
            float2 x0 = tile[a],             x1 = tile[a + 32 * 33],
                   x2 = tile[a + 64 * 33],   x3 = tile[a + 96 * 33];
            float2 w1 = W[p], w2 = W[2 * p], w3 = W[3 * p];
            w1.y = -w1.y; w2.y = -w2.y; w3.y = -w3.y;
            x1 = cmulf(x1, w1); x2 = cmulf(x2, w2); x3 = cmulf(x3, w3);
            float2 t0 = make_float2(x0.x + x2.x, x0.y + x2.y);
            float2 t1 = make_float2(x0.x - x2.x, x0.y - x2.y);
            float2 t2 = make_float2(x1.x + x3.x, x1.y + x3.y);
            float2 t3 = make_float2(x1.x - x3.x, x1.y - x3.y);
            float2 y0 = make_float2(t0.x + t2.x, t0.y + t2.y);
            float2 y2 = make_float2(t0.x - t2.x, t0.y - t2.y);
            float2 y1 = make_float2(t1.x - t3.y, t1.y + t3.x);
            float2 y3 = make_float2(t1.x + t3.y, t1.y - t3.x);
            float2 ys[4] = {y0, y1, y2, y3};
            #pragma unroll
            for (int m = 0; m < 4; ++m) {
                float xr = ys[m].x * s, xi = ys[m].y * s;
                tile[a + m * 32 * 33] =
                    make_float2(sqrtf(fmaf(xr, xr, fmaf(xi, xi, 1e-6f))), 0.0f);
            }
        }
    }
    // forward DIF along pos
    sweep_r4<false,false>(tile, W, 5, 1, 33, 7, tid, 256);
    sweep_r4<false,false>(tile, W, 5, 1, 33, 5, tid, 256);
    sweep_r4<false,false>(tile, W, 5, 1, 33, 3, tid, 256);
    __syncthreads();
    // final r2 fused with store
    for (int q = tid; q < 2048; q += 256) {
        int col = q & 31, bf = q >> 5;
        int p0 = 2 * bf;
        float2 x0 = tile[col + p0 * 33];
        float2 x1 = tile[col + (p0 + 1) * 33];
        T_g[bi * NPIX + p0 * 128 + c0 + col]       = make_float2(x0.x + x1.x, x0.y + x1.y);
        T_g[bi * NPIX + (p0 + 1) * 128 + c0 + col] = make_float2(x0.x - x1.x, x0.y - x1.y);
    }
}

// ---------- phase C: fwd row FFT (DIF), final r2 fused with G output ----------
__global__ void __launch_bounds__(256) scatC_kernel()
{
    __shared__ float2 W[128];
    __shared__ float2 tile[32 * PITCH];
    int tid = threadIdx.x;
    init_W(W, tid);
    int bi = blockIdx.x >> 2, slab = blockIdx.x & 3;
    int b = (bi >= NF) ? 1 : 0;
    int r0 = slab * 32;
    const float2* Xf = Xf_g + b * NPIX;

    __syncthreads();
    for (int q = tid; q < 4096; q += 256) {
        int line = q >> 7, c = q & 127;
        tile[line * PITCH + c] = T_g[bi * NPIX + (r0 + line) * 128 + c];
    }
    sweep_r4<false,false>(tile, W, 5, PITCH, 1, 7, tid, 256);
    sweep_r4<false,false>(tile, W, 5, PITCH, 1, 5, tid, 256);
    sweep_r4<false,false>(tile, W, 5, PITCH, 1, 3, tid, 256);
    __syncthreads();
    float* G = G_g + bi * NPIX;
    for (int q = tid; q < 2048; q += 256) {
        int line = q >> 6, bf = q & 63;
        int c0 = 2 * bf;
        float2 x0 = tile[line * PITCH + c0];
        float2 x1 = tile[line * PITCH + c0 + 1];
        float2 y0 = make_float2(x0.x + x1.x, x0.y + x1.y);
        float2 y1 = make_float2(x0.x - x1.x, x0.y - x1.y);
        int q0 = (r0 + line) * 128 + c0;
        float4 Xp = *(const float4*)&Xf[q0];
        G[q0]     = Xp.x * y0.x + Xp.y * y0.y;
        G[q0 + 1] = Xp.z * y1.x + Xp.w * y1.y;
    }
}

// ---------- split-K GEMM: C[66,33] partials over 256-px chunks ----------
__global__ void __launch_bounds__(256) gemm_kernel()
{
    __shared__ float fs[NF * 260];
    int tid = threadIdx.x, lane = tid & 31, w = tid >> 5;
    int k0 = blockIdx.x * 256;
    for (int idx = tid; idx < NF * 256; idx += 256) {
        int j = idx >> 8, px = idx & 255;
        float f = Fperm_g[j * NPIX + k0 + px];
        fs[j * 260 + px] = f * f;
    }
    __syncthreads();
    for (int grp = w; grp < 17; grp += 8) {
        int r0 = grp * 4;
        int nr = (66 - r0 < 4) ? (66 - r0) : 4;
        float acc[4] = {0.f, 0.f, 0.f, 0.f};
        const float4* fsp = (const float4*)&fs[lane * 260];   // j = lane
        for (int px4 = 0; px4 < 64; ++px4) {
            float4 f = fsp[px4];
            #pragma unroll
            for (int u = 0; u < 4; ++u) {
                if (u < nr) {
                    float4 g = *(const float4*)&G_g[(r0 + u) * NPIX + k0 + px4 * 4];
                    acc[u] += g.x * f.x + g.y * f.y + g.z * f.z + g.w * f.w;
                }
            }
        }
        #pragma unroll
        for (int u = 0; u < 4; ++u)
            if (u < nr)
                partial_g[((r0 + u) * NF + lane) * NCH + blockIdx.x] = acc[u];
        // j = 32 (lowpass), warp-cooperative
        for (int u = 0; u < nr; ++u) {
            float a = 0.f;
            #pragma unroll
            for (int v = 0; v < 8; ++v) {
                int px = lane + 32 * v;
                a += G_g[(r0 + u) * NPIX + k0 + px] * fs[32 * 260 + px];
            }
            #pragma unroll
            for (int o = 16; o > 0; o >>= 1) a += __shfl_down_sync(0xffffffffu, a, o);
            if (lane == 0)
                partial_g[((r0 + u) * NF + 32) * NCH + blockIdx.x] = a;
        }
    }
}

// ---------- sum partials + gather the 672 (i,j) pairs ----------
__global__ void __launch_bounds__(128) gather_kernel(float* __restrict__ out)
{
    int gt = blockIdx.x * 128 + threadIdx.x;
    if (gt >= 2 * NCOEF) return;
    int b = gt / NCOEF, t = gt % NCOEF;

    int j1 = 0, off = 0;
    #pragma unroll
    for (int jj = 0; jj < 4; ++jj) {
        int sz = 8 * ((4 - jj) * 8 + 1);
        if (t < off + sz) { j1 = jj; break; }
        off += sz;
    }
    int c  = (4 - j1) * 8 + 1;
    int l1 = (t - off) / c;
    int r  = (t - off) % c;
    int i  = j1 * 8 + l1;
    int j  = (r == c - 1) ? 32 : (j1 + r / 8) * 8 + (r % 8);

    const float* p = &partial_g[((b * NF + i) * NF + j) * NCH];
    float v = 0.f;
    #pragma unroll
    for (int ch4 = 0; ch4 < NCH / 4; ++ch4) {
        float4 q = *(const float4*)&p[ch4 * 4];
        v += (q.x + q.y) + (q.z + q.w);
    }
    out[gt] = v * (1.0f / (16384.0f * 16384.0f));
}

extern "C" void kernel_launch(void* const* d_in, const int* in_sizes, int n_in,
                              void* d_out, int out_size)
{
    const float* a0 = (const float*)d_in[0];
    const float* a1 = (const float*)d_in[1];
    const float* x       = (in_sizes[0] < in_sizes[1]) ? a0 : a1;
    const float* filters = (in_sizes[0] < in_sizes[1]) ? a1 : a0;

    combo_kernel<<<2 * NF + 16, 256>>>(x, filters);
    fft_cols_kernel<<<16, 256>>>();
    scatA_kernel<<<4 * 2 * NF, 256>>>();
    scatB_kernel<<<4 * 2 * NF, 256>>>();
    scatC_kernel<<<4 * 2 * NF, 256>>>();
    gemm_kernel<<<NCH, 256>>>();
    gather_kernel<<<(2 * NCOEF + 127) / 128, 128>>>((float*)d_out);
}

// round 7
// speedup vs baseline: 1.0181x; 1.0181x over previous
#include <cuda_runtime.h>
#include <math.h>

#define NF     33
#define NPIX   16384
#define NCOEF  672
#define PITCH  129           // float2 pitch for row tiles
#define NCH    64            // split-K chunks in gemm (256 px each)

__device__ __align__(256) float2 XfTmp_g[2 * NPIX];
__device__ __align__(256) float2 Xf_g[2 * NPIX];       // fft2(x), digit-reversed
__device__ __align__(256) float  Fperm_g[NF * NPIX];   // filters, digit-reversed
__device__ __align__(256) float2 T_g[2 * NF * NPIX];   // phase temp (in-place for B)
__device__ __align__(256) float  G_g[2 * NF * NPIX];   // Re(conj(Xf) * XAf)
__device__ __align__(256) float  partial_g[2 * NF * NF * NCH];

__device__ __forceinline__ float2 cmulf(float2 a, float2 b) {
    return make_float2(fmaf(a.x, b.x, -a.y * b.y), fmaf(a.x, b.y, a.y * b.x));
}

// inverse of the DIF(4,4,4,2) digit-reversal: storage pos -> natural freq
__device__ __forceinline__ int invp(int s) {
    return (s >> 5) + (((s >> 3) & 3) << 2) + (((s >> 1) & 3) << 4) + ((s & 1) << 6);
}

__device__ __forceinline__ void init_W(float2* W, int tid) {
    if (tid < 128) {
        float s, c;
        sincosf(-2.0f * 3.14159265358979323846f * (float)tid / 128.0f, &s, &c);
        W[tid] = make_float2(c, s);
    }
}

// Radix-4 sweep over nlines lines of a 128-point axis.
// addr(line, pos) = line*sl + pos*sp. DIF: twiddle after DFT; DIT: before.
template<bool INV, bool DIT>
__device__ __forceinline__ void sweep_r4(float2* t, const float2* W,
                                         int log2nl, int sl, int sp,
                                         int log2L, int tid, int nthr)
{
    int nlines = 1 << log2nl;
    int total  = nlines << 5;
    int lQ = log2L - 2;
    int Qs = (1 << lQ) * sp;
    __syncthreads();
    for (int q = tid; q < total; q += nthr) {
        int line = q & (nlines - 1);
        int bf   = q >> log2nl;
        int p = bf & ((1 << lQ) - 1);
        int g = bf >> lQ;
        int a = line * sl + ((g << log2L) + p) * sp;
        float2 x0 = t[a], x1 = t[a + Qs], x2 = t[a + 2 * Qs], x3 = t[a + 3 * Qs];
        int e = p << (7 - log2L);
        float2 w1 = W[e], w2 = W[2 * e], w3 = W[3 * e];
        if (INV) { w1.y = -w1.y; w2.y = -w2.y; w3.y = -w3.y; }
        if (DIT) { x1 = cmulf(x1, w1); x2 = cmulf(x2, w2); x3 = cmulf(x3, w3); }
        float2 t0 = make_float2(x0.x + x2.x, x0.y + x2.y);
        float2 t1 = make_float2(x0.x - x2.x, x0.y - x2.y);
        float2 t2 = make_float2(x1.x + x3.x, x1.y + x3.y);
        float2 t3 = make_float2(x1.x - x3.x, x1.y - x3.y);
        float2 y0 = make_float2(t0.x + t2.x, t0.y + t2.y);
        float2 y2 = make_float2(t0.x - t2.x, t0.y - t2.y);
        float2 y1, y3;
        if (!INV) { y1 = make_float2(t1.x + t3.y, t1.y - t3.x);
                    y3 = make_float2(t1.x - t3.y, t1.y + t3.x); }
        else      { y1 = make_float2(t1.x - t3.y, t1.y + t3.x);
                    y3 = make_float2(t1.x + t3.y, t1.y - t3.x); }
        if (!DIT) { y1 = cmulf(y1, w1); y2 = cmulf(y2, w2); y3 = cmulf(y3, w3); }
        t[a] = y0; t[a + Qs] = y1; t[a + 2 * Qs] = y2; t[a + 3 * Qs] = y3;
    }
}

// Radix-2 sweep (L=2): no twiddle, identical for DIF/DIT, fwd/inv.
__device__ __forceinline__ void sweep_r2(float2* t, int log2nl, int sl, int sp,
                                         int tid, int nthr)
{
    int nlines = 1 << log2nl;
    int total  = nlines << 6;
    __syncthreads();
    for (int q = tid; q < total; q += nthr) {
        int line = q & (nlines - 1);
        int bf   = q >> log2nl;
        int a = line * sl + (2 * bf) * sp;
        float2 x0 = t[a], x1 = t[a + sp];
        t[a]      = make_float2(x0.x + x1.x, x0.y + x1.y);
        t[a + sp] = make_float2(x0.x - x1.x, x0.y - x1.y);
    }
}

// ---------- kernel: blocks 0..65: filter permute; 66..81: fft rows of x ----------
__global__ void __launch_bounds__(256) combo_kernel(const float* __restrict__ x,
                                                    const float* __restrict__ filters)
{
    __shared__ float2 W[128];
    __shared__ float2 tile[16 * PITCH];
    int tid = threadIdx.x;
    int blk = blockIdx.x;
    if (blk < 2 * NF) {
        int i  = blk >> 1;
        int s0 = (blk & 1) * 8192;
        for (int q = tid; q < 8192; q += 256) {
            int s = s0 + q;
            int kr = invp(s >> 7), kc = invp(s & 127);
            Fperm_g[i * NPIX + s] = __ldg(&filters[i * NPIX + kr * 128 + kc]);
        }
        return;
    }
    int idx = blk - 2 * NF;           // 0..15
    init_W(W, tid);
    int b = idx >> 3, r0 = (idx & 7) * 16;
    for (int q = tid; q < 16 * 128; q += 256) {
        int r = q >> 7, c = q & 127;
        tile[r * PITCH + c] = make_float2(x[b * NPIX + (r0 + r) * 128 + c], 0.0f);
    }
    sweep_r4<false,false>(tile, W, 4, PITCH, 1, 7, tid, 256);
    sweep_r4<false,false>(tile, W, 4, PITCH, 1, 5, tid, 256);
    sweep_r4<false,false>(tile, W, 4, PITCH, 1, 3, tid, 256);
    sweep_r2(tile, 4, PITCH, 1, tid, 256);
    __syncthreads();
    for (int q = tid; q < 16 * 128; q += 256) {
        int r = q >> 7, c = q & 127;
        XfTmp_g[b * NPIX + (r0 + r) * 128 + c] = tile[r * PITCH + c];
    }
}

// ---------- kernel: forward DIF along columns of x ----------
__global__ void __launch_bounds__(256) fft_cols_kernel()
{
    __shared__ float2 W[128];
    __shared__ float2 tile[128 * 17];
    int tid = threadIdx.x;
    init_W(W, tid);
    int b = blockIdx.x >> 3, c0 = (blockIdx.x & 7) * 16;
    for (int q = tid; q < 128 * 16; q += 256) {
        int pos = q >> 4, col = q & 15;
        tile[pos * 17 + col] = XfTmp_g[b * NPIX + pos * 128 + c0 + col];
    }
    sweep_r4<false,false>(tile, W, 4, 1, 17, 7, tid, 256);
    sweep_r4<false,false>(tile, W, 4, 1, 17, 5, tid, 256);
    sweep_r4<false,false>(tile, W, 4, 1, 17, 3, tid, 256);
    sweep_r2(tile, 4, 1, 17, tid, 256);
    __syncthreads();
    for (int q = tid; q < 128 * 16; q += 256) {
        int pos = q >> 4, col = q & 15;
        Xf_g[b * NPIX + pos * 128 + c0 + col] = tile[pos * 17 + col];
    }
}

// ---------- phase A: load F*Xf row-slab, inverse row FFT (DIT), write T ----------
__global__ void __launch_bounds__(256) scatA_kernel()
{
    __shared__ float2 W[128];
    __shared__ float2 tile[32 * PITCH];
    int tid = threadIdx.x;
    init_W(W, tid);
    int bi = blockIdx.x >> 2, slab = blockIdx.x & 3;
    int b = (bi >= NF) ? 1 : 0;
    int i = bi - b * NF;
    int r0 = slab * 32;
    const float2* Xf = Xf_g + b * NPIX;
    const float*  Fp = Fperm_g + i * NPIX;

    // fused load + filter mult + first DIT stage (r2 along row)
    __syncthreads();
    for (int q = tid; q < 2048; q += 256) {
        int line = q >> 6, bf = q & 63;
        int c0 = 2 * bf;
        int q0 = (r0 + line) * 128 + c0;
        float4 Xp = *(const float4*)&Xf[q0];
        float2 fp = *(const float2*)&Fp[q0];
        float2 a0 = make_float2(fp.x * Xp.x, fp.x * Xp.y);
        float2 a1 = make_float2(fp.y * Xp.z, fp.y * Xp.w);
        tile[line * PITCH + c0]     = make_float2(a0.x + a1.x, a0.y + a1.y);
        tile[line * PITCH + c0 + 1] = make_float2(a0.x - a1.x, a0.y - a1.y);
    }
    sweep_r4<true,true>(tile, W, 5, PITCH, 1, 3, tid, 256);
    sweep_r4<true,true>(tile, W, 5, PITCH, 1, 5, tid, 256);
    sweep_r4<true,true>(tile, W, 5, PITCH, 1, 7, tid, 256);
    __syncthreads();
    for (int q = tid; q < 4096; q += 256) {
        int line = q >> 7, c = q & 127;
        T_g[bi * NPIX + (r0 + line) * 128 + c] = tile[line * PITCH + c];
    }
}

// ---------- phase B: per col-slab: inv col FFT (DIT) + abs_eps + fwd col FFT (DIF), in place ----------
__global__ void __launch_bounds__(256) scatB_kernel()
{
    __shared__ float2 W[128];
    __shared__ float2 tile[128 * 33];   // addr = col + pos*33
    int tid = threadIdx.x;
    init_W(W, tid);
    int bi = blockIdx.x >> 2, slab = blockIdx.x & 3;
    int c0 = slab * 32;

    __syncthreads();
    for (int q = tid; q < 4096; q += 256) {
        int col = q & 31, pos = q >> 5;
        tile[col + pos * 33] = T_g[bi * NPIX + pos * 128 + c0 + col];
    }
    // inverse DIT along pos
    sweep_r2(tile, 5, 1, 33, tid, 256);
    sweep_r4<true,true>(tile, W, 5, 1, 33, 3, tid, 256);
    sweep_r4<true,true>(tile, W, 5, 1, 33, 5, tid, 256);
    // last DIT stage (L=128) fused with abs_eps (+ 1/16384 ifft normalization)
    {
        const float s = 1.0f / 16384.0f;
        __syncthreads();
        for (int q = tid; q < 1024; q += 256) {
            int col = q & 31;
            int p   = q >> 5;              // 0..31
            int a = col + p * 33;
            float2 x0 = tile[a],             x1 = tile[a + 32 * 33],
                   x2 = tile[a + 64 * 33],   x3 = tile[a + 96 * 33];
            float2 w1 = W[p], w2 = W[2 * p], w3 = W[3 * p];
            w1.y = -w1.y; w2.y = -w2.y; w3.y = -w3.y;
            x1 = cmulf(x1, w1); x2 = cmulf(x2, w2); x3 = cmulf(x3, w3);
            float2 t0 = make_float2(x0.x + x2.x, x0.y + x2.y);
            float2 t1 = make_float2(x0.x - x2.x, x0.y - x2.y);
            float2 t2 = make_float2(x1.x + x3.x, x1.y + x3.y);
            float2 t3 = make_float2(x1.x - x3.x, x1.y - x3.y);
            float2 y0 = make_float2(t0.x + t2.x, t0.y + t2.y);
            float2 y2 = make_float2(t0.x - t2.x, t0.y - t2.y);
            float2 y1 = make_float2(t1.x - t3.y, t1.y + t3.x);
            float2 y3 = make_float2(t1.x + t3.y, t1.y - t3.x);
            float2 ys[4] = {y0, y1, y2, y3};
            #pragma unroll
            for (int m = 0; m < 4; ++m) {
                float xr = ys[m].x * s, xi = ys[m].y * s;
                tile[a + m * 32 * 33] =
                    make_float2(sqrtf(fmaf(xr, xr, fmaf(xi, xi, 1e-6f))), 0.0f);
            }
        }
    }
    // forward DIF along pos
    sweep_r4<false,false>(tile, W, 5, 1, 33, 7, tid, 256);
    sweep_r4<false,false>(tile, W, 5, 1, 33, 5, tid, 256);
    sweep_r4<false,false>(tile, W, 5, 1, 33, 3, tid, 256);
    __syncthreads();
    // final r2 fused with store
    for (int q = tid; q < 2048; q += 256) {
        int col = q & 31, bf = q >> 5;
        int p0 = 2 * bf;
        float2 x0 = tile[col + p0 * 33];
        float2 x1 = tile[col + (p0 + 1) * 33];
        T_g[bi * NPIX + p0 * 128 + c0 + col]       = make_float2(x0.x + x1.x, x0.y + x1.y);
        T_g[bi * NPIX + (p0 + 1) * 128 + c0 + col] = make_float2(x0.x - x1.x, x0.y - x1.y);
    }
}

// ---------- phase C: fwd row FFT (DIF), final r2 fused with G output ----------
__global__ void __launch_bounds__(256) scatC_kernel()
{
    __shared__ float2 W[128];
    __shared__ float2 tile[32 * PITCH];
    int tid = threadIdx.x;
    init_W(W, tid);
    int bi = blockIdx.x >> 2, slab = blockIdx.x & 3;
    int b = (bi >= NF) ? 1 : 0;
    int r0 = slab * 32;
    const float2* Xf = Xf_g + b * NPIX;

    __syncthreads();
    for (int q = tid; q < 4096; q += 256) {
        int line = q >> 7, c = q & 127;
        tile[line * PITCH + c] = T_g[bi * NPIX + (r0 + line) * 128 + c];
    }
    sweep_r4<false,false>(tile, W, 5, PITCH, 1, 7, tid, 256);
    sweep_r4<false,false>(tile, W, 5, PITCH, 1, 5, tid, 256);
    sweep_r4<false,false>(tile, W, 5, PITCH, 1, 3, tid, 256);
    __syncthreads();
    float* G = G_g + bi * NPIX;
    for (int q = tid; q < 2048; q += 256) {
        int line = q >> 6, bf = q & 63;
        int c0 = 2 * bf;
        float2 x0 = tile[line * PITCH + c0];
        float2 x1 = tile[line * PITCH + c0 + 1];
        float2 y0 = make_float2(x0.x + x1.x, x0.y + x1.y);
        float2 y1 = make_float2(x0.x - x1.x, x0.y - x1.y);
        int q0 = (r0 + line) * 128 + c0;
        float4 Xp = *(const float4*)&Xf[q0];
        G[q0]     = Xp.x * y0.x + Xp.y * y0.y;
        G[q0 + 1] = Xp.z * y1.x + Xp.w * y1.y;
    }
}

// ---------- split-K GEMM: C[66,33] partials over 256-px chunks ----------
__global__ void __launch_bounds__(256) gemm_kernel()
{
    __shared__ float fs[NF * 260];
    int tid = threadIdx.x, lane = tid & 31, w = tid >> 5;
    int k0 = blockIdx.x * 256;
    for (int idx = tid; idx < NF * 256; idx += 256) {
        int j = idx >> 8, px = idx & 255;
        float f = Fperm_g[j * NPIX + k0 + px];
        fs[j * 260 + px] = f * f;
    }
    __syncthreads();
    for (int grp = w; grp < 17; grp += 8) {
        int r0 = grp * 4;
        int nr = (66 - r0 < 4) ? (66 - r0) : 4;
        float acc[4] = {0.f, 0.f, 0.f, 0.f};
        const float4* fsp = (const float4*)&fs[lane * 260];   // j = lane
        for (int px4 = 0; px4 < 64; ++px4) {
            float4 f = fsp[px4];
            #pragma unroll
            for (int u = 0; u < 4; ++u) {
                if (u < nr) {
                    float4 g = *(const float4*)&G_g[(r0 + u) * NPIX + k0 + px4 * 4];
                    acc[u] += g.x * f.x + g.y * f.y + g.z * f.z + g.w * f.w;
                }
            }
        }
        #pragma unroll
        for (int u = 0; u < 4; ++u)
            if (u < nr)
                partial_g[((r0 + u) * NF + lane) * NCH + blockIdx.x] = acc[u];
        // j = 32 (lowpass), warp-cooperative
        for (int u = 0; u < nr; ++u) {
            float a = 0.f;
            #pragma unroll
            for (int v = 0; v < 8; ++v) {
                int px = lane + 32 * v;
                a += G_g[(r0 + u) * NPIX + k0 + px] * fs[32 * 260 + px];
            }
            #pragma unroll
            for (int o = 16; o > 0; o >>= 1) a += __shfl_down_sync(0xffffffffu, a, o);
            if (lane == 0)
                partial_g[((r0 + u) * NF + 32) * NCH + blockIdx.x] = a;
        }
    }
}

// ---------- sum partials + gather the 672 (i,j) pairs ----------
__global__ void __launch_bounds__(128) gather_kernel(float* __restrict__ out)
{
    int gt = blockIdx.x * 128 + threadIdx.x;
    if (gt >= 2 * NCOEF) return;
    int b = gt / NCOEF, t = gt % NCOEF;

    int j1 = 0, off = 0;
    #pragma unroll
    for (int jj = 0; jj < 4; ++jj) {
        int sz = 8 * ((4 - jj) * 8 + 1);
        if (t < off + sz) { j1 = jj; break; }
        off += sz;
    }
    int c  = (4 - j1) * 8 + 1;
    int l1 = (t - off) / c;
    int r  = (t - off) % c;
    int i  = j1 * 8 + l1;
    int j  = (r == c - 1) ? 32 : (j1 + r / 8) * 8 + (r % 8);

    const float* p = &partial_g[((b * NF + i) * NF + j) * NCH];
    float v = 0.f;
    #pragma unroll
    for (int ch4 = 0; ch4 < NCH / 4; ++ch4) {
        float4 q = *(const float4*)&p[ch4 * 4];
        v += (q.x + q.y) + (q.z + q.w);
    }
    out[gt] = v * (1.0f / (16384.0f * 16384.0f));
}

extern "C" void kernel_launch(void* const* d_in, const int* in_sizes, int n_in,
                              void* d_out, int out_size)
{
    const float* a0 = (const float*)d_in[0];
    const float* a1 = (const float*)d_in[1];
    const float* x       = (in_sizes[0] < in_sizes[1]) ? a0 : a1;
    const float* filters = (in_sizes[0] < in_sizes[1]) ? a1 : a0;

    combo_kernel<<<2 * NF + 16, 256>>>(x, filters);
    fft_cols_kernel<<<16, 256>>>();
    scatA_kernel<<<4 * 2 * NF, 256>>>();
    scatB_kernel<<<4 * 2 * NF, 256>>>();
    scatC_kernel<<<4 * 2 * NF, 256>>>();
    gemm_kernel<<<NCH, 256>>>();
    gather_kernel<<<(2 * NCOEF + 127) / 128, 128>>>((float*)d_out);
}

// round 8
// speedup vs baseline: 1.0742x; 1.0550x over previous
#include <cuda_runtime.h>
#include <math.h>

#define NF     33
#define NPIX   16384
#define NCOEF  672
#define PITCH  129           // float2 pitch for row tiles
#define NCH    64            // split-K chunks in gemm (256 px each)

__device__ __align__(256) float2 XfTmp_g[2 * NPIX];
__device__ __align__(256) float2 Xf_g[2 * NPIX];       // fft2(x), digit-reversed
__device__ __align__(256) float  Fperm_g[NF * NPIX];   // filters, digit-reversed
__device__ __align__(256) float  G_g[2 * NF * NPIX];   // Re(conj(Xf) * XAf)
__device__ __align__(256) float  partial_g[2 * NF * NF * NCH];

__device__ __forceinline__ float2 cmulf(float2 a, float2 b) {
    return make_float2(fmaf(a.x, b.x, -a.y * b.y), fmaf(a.x, b.y, a.y * b.x));
}

// inverse of the DIF(4,4,4,2) digit-reversal: storage pos -> natural freq
__device__ __forceinline__ int invp(int s) {
    return (s >> 5) + (((s >> 3) & 3) << 2) + (((s >> 1) & 3) << 4) + ((s & 1) << 6);
}

__device__ __forceinline__ void init_W(float2* W, int tid) {
    if (tid < 128) {
        float s, c;
        sincosf(-2.0f * 3.14159265358979323846f * (float)tid / 128.0f, &s, &c);
        W[tid] = make_float2(c, s);
    }
}

// ---- register butterflies ----
// forward DIF: butterfly then twiddle outputs 1..3
__device__ __forceinline__ void bf4_dif(float2& x0, float2& x1, float2& x2, float2& x3,
                                        float2 w1, float2 w2, float2 w3)
{
    float2 t0 = make_float2(x0.x + x2.x, x0.y + x2.y);
    float2 t1 = make_float2(x0.x - x2.x, x0.y - x2.y);
    float2 t2 = make_float2(x1.x + x3.x, x1.y + x3.y);
    float2 t3 = make_float2(x1.x - x3.x, x1.y - x3.y);
    float2 y0 = make_float2(t0.x + t2.x, t0.y + t2.y);
    float2 y2 = make_float2(t0.x - t2.x, t0.y - t2.y);
    float2 y1 = make_float2(t1.x + t3.y, t1.y - t3.x);
    float2 y3 = make_float2(t1.x - t3.y, t1.y + t3.x);
    x0 = y0; x1 = cmulf(y1, w1); x2 = cmulf(y2, w2); x3 = cmulf(y3, w3);
}

// inverse DIT: conj twiddles applied to inputs 1..3, then inverse butterfly
__device__ __forceinline__ void bf4_dit(float2& x0, float2& x1, float2& x2, float2& x3,
                                        float2 w1, float2 w2, float2 w3)
{
    w1.y = -w1.y; w2.y = -w2.y; w3.y = -w3.y;
    x1 = cmulf(x1, w1); x2 = cmulf(x2, w2); x3 = cmulf(x3, w3);
    float2 t0 = make_float2(x0.x + x2.x, x0.y + x2.y);
    float2 t1 = make_float2(x0.x - x2.x, x0.y - x2.y);
    float2 t2 = make_float2(x1.x + x3.x, x1.y + x3.y);
    float2 t3 = make_float2(x1.x - x3.x, x1.y - x3.y);
    x0 = make_float2(t0.x + t2.x, t0.y + t2.y);
    x2 = make_float2(t0.x - t2.x, t0.y - t2.y);
    x1 = make_float2(t1.x - t3.y, t1.y + t3.x);
    x3 = make_float2(t1.x + t3.y, t1.y - t3.x);
}

__device__ __forceinline__ void bf2(float2& a, float2& b) {
    float2 s = make_float2(a.x + b.x, a.y + b.y);
    float2 d = make_float2(a.x - b.x, a.y - b.y);
    a = s; b = d;
}

// stage pair A: registers r[k] hold points p0 + 8k (k=0..15), p0 in [0,8)
// forward DIF: L=128 (quads k0,k0+4,k0+8,k0+12; e=p0+8k0) then L=32 (quads 4g+m; e=4p0)
__device__ __forceinline__ void stageA_fwd(float2 r[16], const float2* W, int p0)
{
    #pragma unroll
    for (int k0 = 0; k0 < 4; ++k0) {
        int e = p0 + 8 * k0;
        bf4_dif(r[k0], r[k0 + 4], r[k0 + 8], r[k0 + 12], W[e], W[2 * e], W[3 * e]);
    }
    int e = 4 * p0;
    float2 w1 = W[e], w2 = W[2 * e], w3 = W[3 * e];
    #pragma unroll
    for (int g = 0; g < 4; ++g)
        bf4_dif(r[4 * g], r[4 * g + 1], r[4 * g + 2], r[4 * g + 3], w1, w2, w3);
}

// inverse DIT: L=32 first, then L=128 (mirrored order)
__device__ __forceinline__ void stageA_inv(float2 r[16], const float2* W, int p0)
{
    int e = 4 * p0;
    float2 w1 = W[e], w2 = W[2 * e], w3 = W[3 * e];
    #pragma unroll
    for (int g = 0; g < 4; ++g)
        bf4_dit(r[4 * g], r[4 * g + 1], r[4 * g + 2], r[4 * g + 3], w1, w2, w3);
    #pragma unroll
    for (int k0 = 0; k0 < 4; ++k0) {
        int e2 = p0 + 8 * k0;
        bf4_dit(r[k0], r[k0 + 4], r[k0 + 8], r[k0 + 12], W[e2], W[2 * e2], W[3 * e2]);
    }
}

// stage pair B: registers a[m] hold 8 consecutive points 8g + m
// forward DIF: L=8 (quads p2,p2+2,p2+4,p2+6; e=16p2) then L=2 (pairs)
__device__ __forceinline__ void stageB_fwd(float2 a[8], const float2* W)
{
    #pragma unroll
    for (int p2 = 0; p2 < 2; ++p2) {
        int e = 16 * p2;
        bf4_dif(a[p2], a[p2 + 2], a[p2 + 4], a[p2 + 6], W[e], W[2 * e], W[3 * e]);
    }
    #pragma unroll
    for (int h = 0; h < 4; ++h) bf2(a[2 * h], a[2 * h + 1]);
}

// inverse DIT: L=2 first, then L=8
__device__ __forceinline__ void stageB_inv(float2 a[8], const float2* W)
{
    #pragma unroll
    for (int h = 0; h < 4; ++h) bf2(a[2 * h], a[2 * h + 1]);
    #pragma unroll
    for (int p2 = 0; p2 < 2; ++p2) {
        int e = 16 * p2;
        bf4_dit(a[p2], a[p2 + 2], a[p2 + 4], a[p2 + 6], W[e], W[2 * e], W[3 * e]);
    }
}

// ---- shared-memory sweeps for the small x-FFT kernels (round-3 proven code) ----
template<bool INV, bool DIT>
__device__ __forceinline__ void sweep_r4(float2* t, const float2* W,
                                         int log2nl, int sl, int sp,
                                         int log2L, int tid, int nthr)
{
    int nlines = 1 << log2nl;
    int total  = nlines << 5;
    int lQ = log2L - 2;
    int Qs = (1 << lQ) * sp;
    __syncthreads();
    for (int q = tid; q < total; q += nthr) {
        int line = q & (nlines - 1);
        int bf   = q >> log2nl;
        int p = bf & ((1 << lQ) - 1);
        int g = bf >> lQ;
        int a = line * sl + ((g << log2L) + p) * sp;
        float2 x0 = t[a], x1 = t[a + Qs], x2 = t[a + 2 * Qs], x3 = t[a + 3 * Qs];
        int e = p << (7 - log2L);
        float2 w1 = W[e], w2 = W[2 * e], w3 = W[3 * e];
        if (INV) { w1.y = -w1.y; w2.y = -w2.y; w3.y = -w3.y; }
        if (DIT) { x1 = cmulf(x1, w1); x2 = cmulf(x2, w2); x3 = cmulf(x3, w3); }
        float2 t0 = make_float2(x0.x + x2.x, x0.y + x2.y);
        float2 t1 = make_float2(x0.x - x2.x, x0.y - x2.y);
        float2 t2 = make_float2(x1.x + x3.x, x1.y + x3.y);
        float2 t3 = make_float2(x1.x - x3.x, x1.y - x3.y);
        float2 y0 = make_float2(t0.x + t2.x, t0.y + t2.y);
        float2 y2 = make_float2(t0.x - t2.x, t0.y - t2.y);
        float2 y1, y3;
        if (!INV) { y1 = make_float2(t1.x + t3.y, t1.y - t3.x);
                    y3 = make_float2(t1.x - t3.y, t1.y + t3.x); }
        else      { y1 = make_float2(t1.x - t3.y, t1.y + t3.x);
                    y3 = make_float2(t1.x + t3.y, t1.y - t3.x); }
        if (!DIT) { y1 = cmulf(y1, w1); y2 = cmulf(y2, w2); y3 = cmulf(y3, w3); }
        t[a] = y0; t[a + Qs] = y1; t[a + 2 * Qs] = y2; t[a + 3 * Qs] = y3;
    }
}

__device__ __forceinline__ void sweep_r2(float2* t, int log2nl, int sl, int sp,
                                         int tid, int nthr)
{
    int nlines = 1 << log2nl;
    int total  = nlines << 6;
    __syncthreads();
    for (int q = tid; q < total; q += nthr) {
        int line = q & (nlines - 1);
        int bf   = q >> log2nl;
        int a = line * sl + (2 * bf) * sp;
        float2 x0 = t[a], x1 = t[a + sp];
        t[a]      = make_float2(x0.x + x1.x, x0.y + x1.y);
        t[a + sp] = make_float2(x0.x - x1.x, x0.y - x1.y);
    }
}

// ---------- kernel: blocks 0..65: filter permute; 66..81: fft rows of x ----------
__global__ void __launch_bounds__(256) combo_kernel(const float* __restrict__ x,
                                                    const float* __restrict__ filters)
{
    __shared__ float2 W[128];
    __shared__ float2 tile[16 * PITCH];
    int tid = threadIdx.x;
    int blk = blockIdx.x;
    if (blk < 2 * NF) {
        int i  = blk >> 1;
        int s0 = (blk & 1) * 8192;
        for (int q = tid; q < 8192; q += 256) {
            int s = s0 + q;
            int kr = invp(s >> 7), kc = invp(s & 127);
            Fperm_g[i * NPIX + s] = __ldg(&filters[i * NPIX + kr * 128 + kc]);
        }
        return;
    }
    int idx = blk - 2 * NF;           // 0..15
    init_W(W, tid);
    int b = idx >> 3, r0 = (idx & 7) * 16;
    for (int q = tid; q < 16 * 128; q += 256) {
        int r = q >> 7, c = q & 127;
        tile[r * PITCH + c] = make_float2(x[b * NPIX + (r0 + r) * 128 + c], 0.0f);
    }
    sweep_r4<false,false>(tile, W, 4, PITCH, 1, 7, tid, 256);
    sweep_r4<false,false>(tile, W, 4, PITCH, 1, 5, tid, 256);
    sweep_r4<false,false>(tile, W, 4, PITCH, 1, 3, tid, 256);
    sweep_r2(tile, 4, PITCH, 1, tid, 256);
    __syncthreads();
    for (int q = tid; q < 16 * 128; q += 256) {
        int r = q >> 7, c = q & 127;
        XfTmp_g[b * NPIX + (r0 + r) * 128 + c] = tile[r * PITCH + c];
    }
}

// ---------- kernel: forward DIF along columns of x ----------
__global__ void __launch_bounds__(256) fft_cols_kernel()
{
    __shared__ float2 W[128];
    __shared__ float2 tile[128 * 17];
    int tid = threadIdx.x;
    init_W(W, tid);
    int b = blockIdx.x >> 3, c0 = (blockIdx.x & 7) * 16;
    for (int q = tid; q < 128 * 16; q += 256) {
        int pos = q >> 4, col = q & 15;
        tile[pos * 17 + col] = XfTmp_g[b * NPIX + pos * 128 + c0 + col];
    }
    sweep_r4<false,false>(tile, W, 4, 1, 17, 7, tid, 256);
    sweep_r4<false,false>(tile, W, 4, 1, 17, 5, tid, 256);
    sweep_r4<false,false>(tile, W, 4, 1, 17, 3, tid, 256);
    sweep_r2(tile, 4, 1, 17, tid, 256);
    __syncthreads();
    for (int q = tid; q < 128 * 16; q += 256) {
        int pos = q >> 4, col = q & 15;
        Xf_g[b * NPIX + pos * 128 + c0 + col] = tile[pos * 17 + col];
    }
}

// ---------- fused scat: 8 SMEM passes, two FFT stages per pass ----------
__global__ void __launch_bounds__(512) scat_kernel()
{
    extern __shared__ float2 tile[];   // 128 * PITCH
    __shared__ float2 W[128];
    int tid = threadIdx.x;
    init_W(W, tid);
    int blk = blockIdx.x;
    int b = (blk >= NF) ? 1 : 0;
    int i = blk - b * NF;
    const float2* Xf = Xf_g + b * NPIX;
    const float*  Fp = Fperm_g + i * NPIX;

    // pass 1: rows inverse-DIT (L=2, L=8) fused with global load + filter multiply
    __syncthreads();
    for (int idx = tid; idx < 2048; idx += 512) {
        int line = idx & 127, g = idx >> 7;
        int q0 = line * 128 + 8 * g;
        float2 a[8];
        #pragma unroll
        for (int m4 = 0; m4 < 4; ++m4) {
            float4 Xp = *(const float4*)&Xf[q0 + 2 * m4];
            float2 fp = *(const float2*)&Fp[q0 + 2 * m4];
            a[2 * m4]     = make_float2(fp.x * Xp.x, fp.x * Xp.y);
            a[2 * m4 + 1] = make_float2(fp.y * Xp.z, fp.y * Xp.w);
        }
        stageB_inv(a, W);
        #pragma unroll
        for (int m = 0; m < 8; ++m) tile[line * PITCH + 8 * g + m] = a[m];
    }
    // pass 2: rows inverse-DIT (L=32, L=128)
    __syncthreads();
    for (int idx = tid; idx < 1024; idx += 512) {
        int line = idx & 127, p0 = idx >> 7;
        float2 r[16];
        #pragma unroll
        for (int k = 0; k < 16; ++k) r[k] = tile[line * PITCH + p0 + 8 * k];
        stageA_inv(r, W, p0);
        #pragma unroll
        for (int k = 0; k < 16; ++k) tile[line * PITCH + p0 + 8 * k] = r[k];
    }
    // pass 3: cols inverse-DIT (L=2, L=8)
    __syncthreads();
    for (int idx = tid; idx < 2048; idx += 512) {
        int col = idx & 127, g = idx >> 7;
        float2 a[8];
        #pragma unroll
        for (int m = 0; m < 8; ++m) a[m] = tile[col + (8 * g + m) * PITCH];
        stageB_inv(a, W);
        #pragma unroll
        for (int m = 0; m < 8; ++m) tile[col + (8 * g + m) * PITCH] = a[m];
    }
    // pass 4: cols inverse-DIT (L=32, L=128) fused with abs_eps (+ 1/16384 norm)
    __syncthreads();
    {
        const float s = 1.0f / 16384.0f;
        for (int idx = tid; idx < 1024; idx += 512) {
            int col = idx & 127, p0 = idx >> 7;
            float2 r[16];
            #pragma unroll
            for (int k = 0; k < 16; ++k) r[k] = tile[col + (p0 + 8 * k) * PITCH];
            stageA_inv(r, W, p0);
            #pragma unroll
            for (int k = 0; k < 16; ++k) {
                float xr = r[k].x * s, xi = r[k].y * s;
                tile[col + (p0 + 8 * k) * PITCH] =
                    make_float2(sqrtf(fmaf(xr, xr, fmaf(xi, xi, 1e-6f))), 0.0f);
            }
        }
    }
    // pass 5: rows forward-DIF (L=128, L=32)
    __syncthreads();
    for (int idx = tid; idx < 1024; idx += 512) {
        int line = idx & 127, p0 = idx >> 7;
        float2 r[16];
        #pragma unroll
        for (int k = 0; k < 16; ++k) r[k] = tile[line * PITCH + p0 + 8 * k];
        stageA_fwd(r, W, p0);
        #pragma unroll
        for (int k = 0; k < 16; ++k) tile[line * PITCH + p0 + 8 * k] = r[k];
    }
    // pass 6: rows forward-DIF (L=8, L=2)
    __syncthreads();
    for (int idx = tid; idx < 2048; idx += 512) {
        int line = idx & 127, g = idx >> 7;
        float2 a[8];
        #pragma unroll
        for (int m = 0; m < 8; ++m) a[m] = tile[line * PITCH + 8 * g + m];
        stageB_fwd(a, W);
        #pragma unroll
        for (int m = 0; m < 8; ++m) tile[line * PITCH + 8 * g + m] = a[m];
    }
    // pass 7: cols forward-DIF (L=128, L=32)
    __syncthreads();
    for (int idx = tid; idx < 1024; idx += 512) {
        int col = idx & 127, p0 = idx >> 7;
        float2 r[16];
        #pragma unroll
        for (int k = 0; k < 16; ++k) r[k] = tile[col + (p0 + 8 * k) * PITCH];
        stageA_fwd(r, W, p0);
        #pragma unroll
        for (int k = 0; k < 16; ++k) tile[col + (p0 + 8 * k) * PITCH] = r[k];
    }
    // pass 8: cols forward-DIF (L=8, L=2) fused with G output
    __syncthreads();
    {
        float* G = G_g + blk * NPIX;
        for (int idx = tid; idx < 2048; idx += 512) {
            int col = idx & 127, g = idx >> 7;
            float2 a[8];
            #pragma unroll
            for (int m = 0; m < 8; ++m) a[m] = tile[col + (8 * g + m) * PITCH];
            stageB_fwd(a, W);
            #pragma unroll
            for (int m = 0; m < 8; ++m) {
                int q = (8 * g + m) * 128 + col;
                float2 X = Xf[q];
                G[q] = X.x * a[m].x + X.y * a[m].y;
            }
        }
    }
}

// ---------- split-K GEMM: C[66,33] partials over 256-px chunks ----------
__global__ void __launch_bounds__(256) gemm_kernel()
{
    __shared__ float fs[NF * 260];
    int tid = threadIdx.x, lane = tid & 31, w = tid >> 5;
    int k0 = blockIdx.x * 256;
    for (int idx = tid; idx < NF * 256; idx += 256) {
        int j = idx >> 8, px = idx & 255;
        float f = Fperm_g[j * NPIX + k0 + px];
        fs[j * 260 + px] = f * f;
    }
    __syncthreads();
    for (int grp = w; grp < 17; grp += 8) {
        int r0 = grp * 4;
        int nr = (66 - r0 < 4) ? (66 - r0) : 4;
        float acc[4] = {0.f, 0.f, 0.f, 0.f};
        const float4* fsp = (const float4*)&fs[lane * 260];   // j = lane
        for (int px4 = 0; px4 < 64; ++px4) {
            float4 f = fsp[px4];
            #pragma unroll
            for (int u = 0; u < 4; ++u) {
                if (u < nr) {
                    float4 g = *(const float4*)&G_g[(r0 + u) * NPIX + k0 + px4 * 4];
                    acc[u] += g.x * f.x + g.y * f.y + g.z * f.z + g.w * f.w;
                }
            }
        }
        #pragma unroll
        for (int u = 0; u < 4; ++u)
            if (u < nr)
                partial_g[((r0 + u) * NF + lane) * NCH + blockIdx.x] = acc[u];
        // j = 32 (lowpass), warp-cooperative
        for (int u = 0; u < nr; ++u) {
            float a = 0.f;
            #pragma unroll
            for (int v = 0; v < 8; ++v) {
                int px = lane + 32 * v;
                a += G_g[(r0 + u) * NPIX + k0 + px] * fs[32 * 260 + px];
            }
            #pragma unroll
            for (int o = 16; o > 0; o >>= 1) a += __shfl_down_sync(0xffffffffu, a, o);
            if (lane == 0)
                partial_g[((r0 + u) * NF + 32) * NCH + blockIdx.x] = a;
        }
    }
}

// ---------- sum partials + gather the 672 (i,j) pairs ----------
__global__ void __launch_bounds__(128) gather_kernel(float* __restrict__ out)
{
    int gt = blockIdx.x * 128 + threadIdx.x;
    if (gt >= 2 * NCOEF) return;
    int b = gt / NCOEF, t = gt % NCOEF;

    int j1 = 0, off = 0;
    #pragma unroll
    for (int jj = 0; jj < 4; ++jj) {
        int sz = 8 * ((4 - jj) * 8 + 1);
        if (t < off + sz) { j1 = jj; break; }
        off += sz;
    }
    int c  = (4 - j1) * 8 + 1;
    int l1 = (t - off) / c;
    int r  = (t - off) % c;
    int i  = j1 * 8 + l1;
    int j  = (r == c - 1) ? 32 : (j1 + r / 8) * 8 + (r % 8);

    const float* p = &partial_g[((b * NF + i) * NF + j) * NCH];
    float v = 0.f;
    #pragma unroll
    for (int ch4 = 0; ch4 < NCH / 4; ++ch4) {
        float4 q = *(const float4*)&p[ch4 * 4];
        v += (q.x + q.y) + (q.z + q.w);
    }
    out[gt] = v * (1.0f / (16384.0f * 16384.0f));
}

extern "C" void kernel_launch(void* const* d_in, const int* in_sizes, int n_in,
                              void* d_out, int out_size)
{
    const float* a0 = (const float*)d_in[0];
    const float* a1 = (const float*)d_in[1];
    const float* x       = (in_sizes[0] < in_sizes[1]) ? a0 : a1;
    const float* filters = (in_sizes[0] < in_sizes[1]) ? a1 : a0;

    size_t smem = (size_t)128 * PITCH * sizeof(float2);   // 132096 B
    cudaFuncSetAttribute(scat_kernel, cudaFuncAttributeMaxDynamicSharedMemorySize, (int)smem);

    combo_kernel<<<2 * NF + 16, 256>>>(x, filters);
    fft_cols_kernel<<<16, 256>>>();
    scat_kernel<<<2 * NF, 512, smem>>>();
    gemm_kernel<<<NCH, 256>>>();
    gather_kernel<<<(2 * NCOEF + 127) / 128, 128>>>((float*)d_out);
}

// round 10
// speedup vs baseline: 1.7179x; 1.5993x over previous
#include <cuda_runtime.h>
#include <math.h>

#define NF     33
#define NPIX   16384
#define NCOEF  672
#define PITCH  129           // float2 pitch for row tiles
#define NCH    128           // split-K chunks in gemm (128 px each)

__device__ __align__(256) float2 XfTmp_g[2 * NPIX];
__device__ __align__(256) float2 Xf_g[2 * NPIX];       // fft2(x), digit-reversed
__device__ __align__(256) float  Fperm_g[NF * NPIX];   // filters, digit-reversed
__device__ __align__(256) float  G_g[2 * NF * NPIX];   // Re(conj(Xf) * XAf)
__device__ __align__(256) float  partial_g[2 * NF * NF * NCH];

__device__ __forceinline__ float2 cmulf(float2 a, float2 b) {
    return make_float2(fmaf(a.x, b.x, -a.y * b.y), fmaf(a.x, b.y, a.y * b.x));
}

// inverse of the DIF(4,4,4,2) digit-reversal: storage pos -> natural freq
__device__ __forceinline__ int invp(int s) {
    return (s >> 5) + (((s >> 3) & 3) << 2) + (((s >> 1) & 3) << 4) + ((s & 1) << 6);
}

__device__ __forceinline__ void init_W(float2* W, int tid) {
    if (tid < 128) {
        float s, c;
        sincosf(-2.0f * 3.14159265358979323846f * (float)tid / 128.0f, &s, &c);
        W[tid] = make_float2(c, s);
    }
}

// ---- register butterflies ----
__device__ __forceinline__ void bf4_dif(float2& x0, float2& x1, float2& x2, float2& x3,
                                        float2 w1, float2 w2, float2 w3)
{
    float2 t0 = make_float2(x0.x + x2.x, x0.y + x2.y);
    float2 t1 = make_float2(x0.x - x2.x, x0.y - x2.y);
    float2 t2 = make_float2(x1.x + x3.x, x1.y + x3.y);
    float2 t3 = make_float2(x1.x - x3.x, x1.y - x3.y);
    float2 y0 = make_float2(t0.x + t2.x, t0.y + t2.y);
    float2 y2 = make_float2(t0.x - t2.x, t0.y - t2.y);
    float2 y1 = make_float2(t1.x + t3.y, t1.y - t3.x);
    float2 y3 = make_float2(t1.x - t3.y, t1.y + t3.x);
    x0 = y0; x1 = cmulf(y1, w1); x2 = cmulf(y2, w2); x3 = cmulf(y3, w3);
}

__device__ __forceinline__ void bf4_dit(float2& x0, float2& x1, float2& x2, float2& x3,
                                        float2 w1, float2 w2, float2 w3)
{
    w1.y = -w1.y; w2.y = -w2.y; w3.y = -w3.y;
    x1 = cmulf(x1, w1); x2 = cmulf(x2, w2); x3 = cmulf(x3, w3);
    float2 t0 = make_float2(x0.x + x2.x, x0.y + x2.y);
    float2 t1 = make_float2(x0.x - x2.x, x0.y - x2.y);
    float2 t2 = make_float2(x1.x + x3.x, x1.y + x3.y);
    float2 t3 = make_float2(x1.x - x3.x, x1.y - x3.y);
    x0 = make_float2(t0.x + t2.x, t0.y + t2.y);
    x2 = make_float2(t0.x - t2.x, t0.y - t2.y);
    x1 = make_float2(t1.x - t3.y, t1.y + t3.x);
    x3 = make_float2(t1.x + t3.y, t1.y - t3.x);
}

__device__ __forceinline__ void bf2(float2& a, float2& b) {
    float2 s = make_float2(a.x + b.x, a.y + b.y);
    float2 d = make_float2(a.x - b.x, a.y - b.y);
    a = s; b = d;
}

// stage pair A: registers r[k] hold points p0 + 8k (k=0..15), p0 in [0,8)
__device__ __forceinline__ void stageA_fwd(float2 r[16], const float2* W, int p0)
{
    #pragma unroll
    for (int k0 = 0; k0 < 4; ++k0) {
        int e = p0 + 8 * k0;
        bf4_dif(r[k0], r[k0 + 4], r[k0 + 8], r[k0 + 12], W[e], W[2 * e], W[3 * e]);
    }
    int e = 4 * p0;
    float2 w1 = W[e], w2 = W[2 * e], w3 = W[3 * e];
    #pragma unroll
    for (int g = 0; g < 4; ++g)
        bf4_dif(r[4 * g], r[4 * g + 1], r[4 * g + 2], r[4 * g + 3], w1, w2, w3);
}

__device__ __forceinline__ void stageA_inv(float2 r[16], const float2* W, int p0)
{
    int e = 4 * p0;
    float2 w1 = W[e], w2 = W[2 * e], w3 = W[3 * e];
    #pragma unroll
    for (int g = 0; g < 4; ++g)
        bf4_dit(r[4 * g], r[4 * g + 1], r[4 * g + 2], r[4 * g + 3], w1, w2, w3);
    #pragma unroll
    for (int k0 = 0; k0 < 4; ++k0) {
        int e2 = p0 + 8 * k0;
        bf4_dit(r[k0], r[k0 + 4], r[k0 + 8], r[k0 + 12], W[e2], W[2 * e2], W[3 * e2]);
    }
}

// stage pair B: registers a[m] hold 8 consecutive points 8g + m
__device__ __forceinline__ void stageB_fwd(float2 a[8], const float2* W)
{
    #pragma unroll
    for (int p2 = 0; p2 < 2; ++p2) {
        int e = 16 * p2;
        bf4_dif(a[p2], a[p2 + 2], a[p2 + 4], a[p2 + 6], W[e], W[2 * e], W[3 * e]);
    }
    #pragma unroll
    for (int h = 0; h < 4; ++h) bf2(a[2 * h], a[2 * h + 1]);
}

__device__ __forceinline__ void stageB_inv(float2 a[8], const float2* W)
{
    #pragma unroll
    for (int h = 0; h < 4; ++h) bf2(a[2 * h], a[2 * h + 1]);
    #pragma unroll
    for (int p2 = 0; p2 < 2; ++p2) {
        int e = 16 * p2;
        bf4_dit(a[p2], a[p2 + 2], a[p2 + 4], a[p2 + 6], W[e], W[2 * e], W[3 * e]);
    }
}

// ---- shared-memory sweeps for the small x-FFT kernels ----
template<bool INV, bool DIT>
__device__ __forceinline__ void sweep_r4(float2* t, const float2* W,
                                         int log2nl, int sl, int sp,
                                         int log2L, int tid, int nthr)
{
    int nlines = 1 << log2nl;
    int total  = nlines << 5;
    int lQ = log2L - 2;
    int Qs = (1 << lQ) * sp;
    __syncthreads();
    for (int q = tid; q < total; q += nthr) {
        int line = q & (nlines - 1);
        int bf   = q >> log2nl;
        int p = bf & ((1 << lQ) - 1);
        int g = bf >> lQ;
        int a = line * sl + ((g << log2L) + p) * sp;
        float2 x0 = t[a], x1 = t[a + Qs], x2 = t[a + 2 * Qs], x3 = t[a + 3 * Qs];
        int e = p << (7 - log2L);
        float2 w1 = W[e], w2 = W[2 * e], w3 = W[3 * e];
        if (INV) { w1.y = -w1.y; w2.y = -w2.y; w3.y = -w3.y; }
        if (DIT) { x1 = cmulf(x1, w1); x2 = cmulf(x2, w2); x3 = cmulf(x3, w3); }
        float2 t0 = make_float2(x0.x + x2.x, x0.y + x2.y);
        float2 t1 = make_float2(x0.x - x2.x, x0.y - x2.y);
        float2 t2 = make_float2(x1.x + x3.x, x1.y + x3.y);
        float2 t3 = make_float2(x1.x - x3.x, x1.y - x3.y);
        float2 y0 = make_float2(t0.x + t2.x, t0.y + t2.y);
        float2 y2 = make_float2(t0.x - t2.x, t0.y - t2.y);
        float2 y1, y3;
        if (!INV) { y1 = make_float2(t1.x + t3.y, t1.y - t3.x);
                    y3 = make_float2(t1.x - t3.y, t1.y + t3.x); }
        else      { y1 = make_float2(t1.x - t3.y, t1.y + t3.x);
                    y3 = make_float2(t1.x + t3.y, t1.y - t3.x); }
        if (!DIT) { y1 = cmulf(y1, w1); y2 = cmulf(y2, w2); y3 = cmulf(y3, w3); }
        t[a] = y0; t[a + Qs] = y1; t[a + 2 * Qs] = y2; t[a + 3 * Qs] = y3;
    }
}

__device__ __forceinline__ void sweep_r2(float2* t, int log2nl, int sl, int sp,
                                         int tid, int nthr)
{
    int nlines = 1 << log2nl;
    int total  = nlines << 6;
    __syncthreads();
    for (int q = tid; q < total; q += nthr) {
        int line = q & (nlines - 1);
        int bf   = q >> log2nl;
        int a = line * sl + (2 * bf) * sp;
        float2 x0 = t[a], x1 = t[a + sp];
        t[a]      = make_float2(x0.x + x1.x, x0.y + x1.y);
        t[a + sp] = make_float2(x0.x - x1.x, x0.y - x1.y);
    }
}

// ---------- kernel: blocks 0..65: filter permute; 66..81: fft rows of x ----------
__global__ void __launch_bounds__(256) combo_kernel(const float* __restrict__ x,
                                                    const float* __restrict__ filters)
{
    __shared__ float2 W[128];
    __shared__ float2 tile[16 * PITCH];
    int tid = threadIdx.x;
    int blk = blockIdx.x;
    if (blk < 2 * NF) {
        int i  = blk >> 1;
        int s0 = (blk & 1) * 8192;
        for (int q = tid; q < 8192; q += 256) {
            int s = s0 + q;
            int kr = invp(s >> 7), kc = invp(s & 127);
            Fperm_g[i * NPIX + s] = __ldg(&filters[i * NPIX + kr * 128 + kc]);
        }
        return;
    }
    int idx = blk - 2 * NF;           // 0..15
    init_W(W, tid);
    int b = idx >> 3, r0 = (idx & 7) * 16;
    for (int q = tid; q < 16 * 128; q += 256) {
        int r = q >> 7, c = q & 127;
        tile[r * PITCH + c] = make_float2(x[b * NPIX + (r0 + r) * 128 + c], 0.0f);
    }
    sweep_r4<false,false>(tile, W, 4, PITCH, 1, 7, tid, 256);
    sweep_r4<false,false>(tile, W, 4, PITCH, 1, 5, tid, 256);
    sweep_r4<false,false>(tile, W, 4, PITCH, 1, 3, tid, 256);
    sweep_r2(tile, 4, PITCH, 1, tid, 256);
    __syncthreads();
    for (int q = tid; q < 16 * 128; q += 256) {
        int r = q >> 7, c = q & 127;
        XfTmp_g[b * NPIX + (r0 + r) * 128 + c] = tile[r * PITCH + c];
    }
}

// ---------- kernel: forward DIF along columns of x ----------
__global__ void __launch_bounds__(256) fft_cols_kernel()
{
    __shared__ float2 W[128];
    __shared__ float2 tile[128 * 17];
    int tid = threadIdx.x;
    init_W(W, tid);
    int b = blockIdx.x >> 3, c0 = (blockIdx.x & 7) * 16;
    for (int q = tid; q < 128 * 16; q += 256) {
        int pos = q >> 4, col = q & 15;
        tile[pos * 17 + col] = XfTmp_g[b * NPIX + pos * 128 + c0 + col];
    }
    sweep_r4<false,false>(tile, W, 4, 1, 17, 7, tid, 256);
    sweep_r4<false,false>(tile, W, 4, 1, 17, 5, tid, 256);
    sweep_r4<false,false>(tile, W, 4, 1, 17, 3, tid, 256);
    sweep_r2(tile, 4, 1, 17, tid, 256);
    __syncthreads();
    for (int q = tid; q < 128 * 16; q += 256) {
        int pos = q >> 4, col = q & 15;
        Xf_g[b * NPIX + pos * 128 + c0 + col] = tile[pos * 17 + col];
    }
}

// ---------- fused scat: 8 SMEM passes, two FFT stages per pass ----------
__global__ void __launch_bounds__(512) scat_kernel()
{
    extern __shared__ float2 tile[];   // 128 * PITCH
    __shared__ float2 W[128];
    int tid = threadIdx.x;
    init_W(W, tid);
    int blk = blockIdx.x;
    int b = (blk >= NF) ? 1 : 0;
    int i = blk - b * NF;
    const float2* Xf = Xf_g + b * NPIX;
    const float*  Fp = Fperm_g + i * NPIX;

    // pass 1: rows inverse-DIT (L=2, L=8) fused with global load + filter multiply
    __syncthreads();
    for (int idx = tid; idx < 2048; idx += 512) {
        int line = idx & 127, g = idx >> 7;
        int q0 = line * 128 + 8 * g;
        float2 a[8];
        #pragma unroll
        for (int m4 = 0; m4 < 4; ++m4) {
            float4 Xp = *(const float4*)&Xf[q0 + 2 * m4];
            float2 fp = *(const float2*)&Fp[q0 + 2 * m4];
            a[2 * m4]     = make_float2(fp.x * Xp.x, fp.x * Xp.y);
            a[2 * m4 + 1] = make_float2(fp.y * Xp.z, fp.y * Xp.w);
        }
        stageB_inv(a, W);
        #pragma unroll
        for (int m = 0; m < 8; ++m) tile[line * PITCH + 8 * g + m] = a[m];
    }
    // pass 2: rows inverse-DIT (L=32, L=128)
    __syncthreads();
    for (int idx = tid; idx < 1024; idx += 512) {
        int line = idx & 127, p0 = idx >> 7;
        float2 r[16];
        #pragma unroll
        for (int k = 0; k < 16; ++k) r[k] = tile[line * PITCH + p0 + 8 * k];
        stageA_inv(r, W, p0);
        #pragma unroll
        for (int k = 0; k < 16; ++k) tile[line * PITCH + p0 + 8 * k] = r[k];
    }
    // pass 3: cols inverse-DIT (L=2, L=8)
    __syncthreads();
    for (int idx = tid; idx < 2048; idx += 512) {
        int col = idx & 127, g = idx >> 7;
        float2 a[8];
        #pragma unroll
        for (int m = 0; m < 8; ++m) a[m] = tile[col + (8 * g + m) * PITCH];
        stageB_inv(a, W);
        #pragma unroll
        for (int m = 0; m < 8; ++m) tile[col + (8 * g + m) * PITCH] = a[m];
    }
    // pass 4: cols inverse-DIT (L=32, L=128) fused with abs_eps (+ 1/16384 norm)
    __syncthreads();
    {
        const float s = 1.0f / 16384.0f;
        for (int idx = tid; idx < 1024; idx += 512) {
            int col = idx & 127, p0 = idx >> 7;
            float2 r[16];
            #pragma unroll
            for (int k = 0; k < 16; ++k) r[k] = tile[col + (p0 + 8 * k) * PITCH];
            stageA_inv(r, W, p0);
            #pragma unroll
            for (int k = 0; k < 16; ++k) {
                float xr = r[k].x * s, xi = r[k].y * s;
                tile[col + (p0 + 8 * k) * PITCH] =
                    make_float2(sqrtf(fmaf(xr, xr, fmaf(xi, xi, 1e-6f))), 0.0f);
            }
        }
    }
    // pass 5: rows forward-DIF (L=128, L=32)
    __syncthreads();
    for (int idx = tid; idx < 1024; idx += 512) {
        int line = idx & 127, p0 = idx >> 7;
        float2 r[16];
        #pragma unroll
        for (int k = 0; k < 16; ++k) r[k] = tile[line * PITCH + p0 + 8 * k];
        stageA_fwd(r, W, p0);
        #pragma unroll
        for (int k = 0; k < 16; ++k) tile[line * PITCH + p0 + 8 * k] = r[k];
    }
    // pass 6: rows forward-DIF (L=8, L=2)
    __syncthreads();
    for (int idx = tid; idx < 2048; idx += 512) {
        int line = idx & 127, g = idx >> 7;
        float2 a[8];
        #pragma unroll
        for (int m = 0; m < 8; ++m) a[m] = tile[line * PITCH + 8 * g + m];
        stageB_fwd(a, W);
        #pragma unroll
        for (int m = 0; m < 8; ++m) tile[line * PITCH + 8 * g + m] = a[m];
    }
    // pass 7: cols forward-DIF (L=128, L=32)
    __syncthreads();
    for (int idx = tid; idx < 1024; idx += 512) {
        int col = idx & 127, p0 = idx >> 7;
        float2 r[16];
        #pragma unroll
        for (int k = 0; k < 16; ++k) r[k] = tile[col + (p0 + 8 * k) * PITCH];
        stageA_fwd(r, W, p0);
        #pragma unroll
        for (int k = 0; k < 16; ++k) tile[col + (p0 + 8 * k) * PITCH] = r[k];
    }
    // pass 8: cols forward-DIF (L=8, L=2) fused with G output
    __syncthreads();
    {
        float* G = G_g + blk * NPIX;
        for (int idx = tid; idx < 2048; idx += 512) {
            int col = idx & 127, g = idx >> 7;
            float2 a[8];
            #pragma unroll
            for (int m = 0; m < 8; ++m) a[m] = tile[col + (8 * g + m) * PITCH];
            stageB_fwd(a, W);
            #pragma unroll
            for (int m = 0; m < 8; ++m) {
                int q = (8 * g + m) * 128 + col;
                float2 X = Xf[q];
                G[q] = X.x * a[m].x + X.y * a[m].y;
            }
        }
    }
}

// ---------- register-blocked split-K GEMM ----------
// C[66,33] = G[66,K] * Fsq[33,K]^T, chunked over K (128 px per block).
// SMEM: gs[px][row] (transposed G chunk, stride 68), fsm[px][j] (stride 36).
// 153 active threads each own a 4x4 (row,j) accumulator tile.
__global__ void __launch_bounds__(256) gemm_kernel()
{
    extern __shared__ float sm[];
    float* gs  = sm;                 // 128 * 68
    float* fsm = sm + 128 * 68;      // 128 * 36
    int tid = threadIdx.x;
    int k0 = blockIdx.x * 128;

    for (int idx = tid; idx < 66 * 128; idx += 256) {
        int row = idx >> 7, px = idx & 127;
        gs[px * 68 + row] = G_g[row * NPIX + k0 + px];
    }
    for (int px = tid; px < 128; px += 256) {
        gs[px * 68 + 66] = 0.0f; gs[px * 68 + 67] = 0.0f;
        fsm[px * 36 + 33] = 0.0f; fsm[px * 36 + 34] = 0.0f; fsm[px * 36 + 35] = 0.0f;
    }
    for (int idx = tid; idx < NF * 128; idx += 256) {
        int j = idx >> 7, px = idx & 127;
        float f = Fperm_g[j * NPIX + k0 + px];
        fsm[px * 36 + j] = f * f;
    }
    __syncthreads();
    if (tid >= 153) return;          // no further barriers

    int tx = tid % 9, ty = tid / 9;  // j-group 0..8, row-group 0..16
    float acc[4][4] = {};
    #pragma unroll 4
    for (int px = 0; px < 128; ++px) {
        float4 g = *(const float4*)&gs[px * 68 + 4 * ty];
        float4 f = *(const float4*)&fsm[px * 36 + 4 * tx];
        acc[0][0] = fmaf(g.x, f.x, acc[0][0]); acc[0][1] = fmaf(g.x, f.y, acc[0][1]);
        acc[0][2] = fmaf(g.x, f.z, acc[0][2]); acc[0][3] = fmaf(g.x, f.w, acc[0][3]);
        acc[1][0] = fmaf(g.y, f.x, acc[1][0]); acc[1][1] = fmaf(g.y, f.y, acc[1][1]);
        acc[1][2] = fmaf(g.y, f.z, acc[1][2]); acc[1][3] = fmaf(g.y, f.w, acc[1][3]);
        acc[2][0] = fmaf(g.z, f.x, acc[2][0]); acc[2][1] = fmaf(g.z, f.y, acc[2][1]);
        acc[2][2] = fmaf(g.z, f.z, acc[2][2]); acc[2][3] = fmaf(g.z, f.w, acc[2][3]);
        acc[3][0] = fmaf(g.w, f.x, acc[3][0]); acc[3][1] = fmaf(g.w, f.y, acc[3][1]);
        acc[3][2] = fmaf(g.w, f.z, acc[3][2]); acc[3][3] = fmaf(g.w, f.w, acc[3][3]);
    }
    #pragma unroll
    for (int r = 0; r < 4; ++r) {
        int row = 4 * ty + r;
        if (row >= 66) break;
        #pragma unroll
        for (int c = 0; c < 4; ++c) {
            int j = 4 * tx + c;
            if (j < NF)
                partial_g[(row * NF + j) * NCH + blockIdx.x] = acc[r][c];
        }
    }
}

// ---------- sum partials + gather the 672 (i,j) pairs ----------
__global__ void __launch_bounds__(128) gather_kernel(float* __restrict__ out)
{
    int gt = blockIdx.x * 128 + threadIdx.x;
    if (gt >= 2 * NCOEF) return;
    int b = gt / NCOEF, t = gt % NCOEF;

    int j1 = 0, off = 0;
    #pragma unroll
    for (int jj = 0; jj < 4; ++jj) {
        int sz = 8 * ((4 - jj) * 8 + 1);
        if (t < off + sz) { j1 = jj; break; }
        off += sz;
    }
    int c  = (4 - j1) * 8 + 1;
    int l1 = (t - off) / c;
    int r  = (t - off) % c;
    int i  = j1 * 8 + l1;
    int j  = (r == c - 1) ? 32 : (j1 + r / 8) * 8 + (r % 8);

    const float* p = &partial_g[((b * NF + i) * NF + j) * NCH];
    float v = 0.f;
    #pragma unroll
    for (int ch4 = 0; ch4 < NCH / 4; ++ch4) {
        float4 q = *(const float4*)&p[ch4 * 4];
        v += (q.x + q.y) + (q.z + q.w);
    }
    out[gt] = v * (1.0f / (16384.0f * 16384.0f));
}

extern "C" void kernel_launch(void* const* d_in, const int* in_sizes, int n_in,
                              void* d_out, int out_size)
{
    const float* a0 = (const float*)d_in[0];
    const float* a1 = (const float*)d_in[1];
    const float* x       = (in_sizes[0] < in_sizes[1]) ? a0 : a1;
    const float* filters = (in_sizes[0] < in_sizes[1]) ? a1 : a0;

    size_t smem = (size_t)128 * PITCH * sizeof(float2);          // 132096 B
    size_t gsm  = (size_t)(128 * 68 + 128 * 36) * sizeof(float); // 53248 B
    cudaFuncSetAttribute(scat_kernel, cudaFuncAttributeMaxDynamicSharedMemorySize, (int)smem);
    cudaFuncSetAttribute(gemm_kernel, cudaFuncAttributeMaxDynamicSharedMemorySize, (int)gsm);

    combo_kernel<<<2 * NF + 16, 256>>>(x, filters);
    fft_cols_kernel<<<16, 256>>>();
    scat_kernel<<<2 * NF, 512, smem>>>();
    gemm_kernel<<<NCH, 256, gsm>>>();
    gather_kernel<<<(2 * NCOEF + 127) / 128, 128>>>((float*)d_out);
}